// round 2
// baseline (speedup 1.0000x reference)
#include <cuda_runtime.h>
#include <math.h>

#define TT 4096
#define BB 32
#define DD 128
#define D3 384

// Scratch for xi = x @ Wi + bi : [T, B, 3D] fp32 = 201 MB (static __device__,
// per allocation-guard rules).
__device__ float g_xi[(size_t)TT * BB * D3];
__device__ int g_reset_mode; // 0 = int32, 1 = float32, 2 = uint8/bool

// ---------------------------------------------------------------------------
// Probe the resets buffer dtype. Reads exactly 32768 uint32 = 128 KB, which is
// in-bounds for uint8 (131072 B), int32 (512 KB) and float32 (512 KB) layouts.
// ~1% reset density guarantees nonzero entries in the probed region.
// ---------------------------------------------------------------------------
__global__ void probe_resets_kernel(const unsigned int* __restrict__ r) {
    __shared__ int s_not01, s_notf;
    if (threadIdx.x == 0) { s_not01 = 0; s_notf = 0; }
    __syncthreads();
    int not01 = 0, notf = 0;
    for (int i = threadIdx.x; i < 32768; i += blockDim.x) {
        unsigned v = r[i];
        if (v != 0u && v != 1u) not01 = 1;
        if (v != 0u && v != 0x3F800000u) notf = 1;
    }
    if (not01) atomicOr(&s_not01, 1);
    if (notf)  atomicOr(&s_notf, 1);
    __syncthreads();
    if (threadIdx.x == 0) {
        int mode;
        if (!s_not01)     mode = 0;  // all values in {0,1}      -> int32
        else if (!s_notf) mode = 1;  // all in {0, 1.0f bits}    -> float32
        else              mode = 2;  // mixed byte patterns      -> uint8
        g_reset_mode = mode;
    }
}

__device__ __forceinline__ int read_reset(const void* r, int idx, int mode) {
    if (mode == 0) return ((const int*)r)[idx] != 0;
    if (mode == 1) return ((const float*)r)[idx] != 0.0f;
    return ((const unsigned char*)r)[idx] != 0;
}

// ---------------------------------------------------------------------------
// xi = x @ Wi + bi.  Thread j holds Wi[:,j] in 128 registers; x rows broadcast
// from shared via LDS.128. 2 rows per iteration to amortize barriers.
// ---------------------------------------------------------------------------
__global__ __launch_bounds__(384, 1)
void gemm_xi_kernel(const float* __restrict__ x,
                    const float* __restrict__ Wi,
                    const float* __restrict__ bi) {
    __shared__ float xs[2][DD];
    const int j = threadIdx.x;

    float w[128];
#pragma unroll
    for (int k = 0; k < 128; k++) w[k] = Wi[k * D3 + j];
    const float bj = bi[j];

    const int R = TT * BB;
    const int per = (R + gridDim.x - 1) / gridDim.x;
    const int r0 = blockIdx.x * per;
    const int r1 = min(r0 + per, R);

    for (int r = r0; r < r1; r += 2) {
        if (j < 256) {
            int rr = r + (j >> 7);
            int kk = j & 127;
            xs[j >> 7][kk] = (rr < r1) ? x[(size_t)rr * DD + kk] : 0.0f;
        }
        __syncthreads();

        float a0 = bj, a1 = bj;
        const float4* x0 = (const float4*)xs[0];
        const float4* x1 = (const float4*)xs[1];
#pragma unroll
        for (int k = 0; k < 32; k++) {
            float4 v0 = x0[k];
            float4 v1 = x1[k];
            a0 += w[4 * k + 0] * v0.x; a1 += w[4 * k + 0] * v1.x;
            a0 += w[4 * k + 1] * v0.y; a1 += w[4 * k + 1] * v1.y;
            a0 += w[4 * k + 2] * v0.z; a1 += w[4 * k + 2] * v1.z;
            a0 += w[4 * k + 3] * v0.w; a1 += w[4 * k + 3] * v1.w;
        }
        g_xi[(size_t)r * D3 + j] = a0;
        if (r + 1 < r1) g_xi[(size_t)(r + 1) * D3 + j] = a1;
        __syncthreads();
    }
}

// ---------------------------------------------------------------------------
// GRU scan. One CTA per batch element. 384 threads: thread j owns Wh[:,j] in
// registers and computes hh[j] = (xi_t[j] | bhn) + <Wh[:,j], h>. Threads 0..127
// then do the gate math and write the new hidden state (double-buffered in
// shared). xi / resets for step t+1 are prefetched during step t's dot phase.
// ---------------------------------------------------------------------------
__global__ __launch_bounds__(384, 1)
void gru_scan_kernel(const void* __restrict__ resets,
                     const float* __restrict__ Wh,
                     const float* __restrict__ bhn,
                     float* __restrict__ ys) {
    __shared__ float h[2][DD];
    __shared__ float hh[D3];

    const int b = blockIdx.x;
    const int j = threadIdx.x;
    const int d = j & 127;
    const int g = j >> 7;           // 0 = r-gate col, 1 = z-gate col, 2 = n-gate col
    const int mode = g_reset_mode;

    float w[128];
#pragma unroll
    for (int k = 0; k < 128; k++) w[k] = Wh[k * D3 + j];
    const float bn = (g == 2) ? bhn[d] : 0.0f;

    if (j < DD) h[0][j] = 0.0f;

    // Prefetch t = 0 operands.
    const float* xi = g_xi;
    size_t base0 = (size_t)b * D3;
    float px = 0.0f, pxn = 0.0f;
    if (g == 0)      { px = xi[base0 + d]; pxn = xi[base0 + 256 + d]; }
    else if (g == 1) { px = xi[base0 + 128 + d]; }
    int rst = read_reset(resets, b, mode);
    __syncthreads();

    int p = 0;
    for (int t = 0; t < TT; t++) {
        // Prefetch step t+1 (hidden behind the dot phase).
        float npx = 0.0f, npxn = 0.0f;
        int nrst = 0;
        if (t + 1 < TT) {
            size_t nb = ((size_t)(t + 1) * BB + b) * D3;
            if (g == 0)      { npx = xi[nb + d]; npxn = xi[nb + 256 + d]; }
            else if (g == 1) { npx = xi[nb + 128 + d]; }
            nrst = read_reset(resets, (t + 1) * BB + b, mode);
        }

        // hh[j] = base + <Wh[:,j], h>, with h == 0 on reset (skip the dot).
        float a0 = 0.0f, a1 = 0.0f, a2 = 0.0f, a3 = 0.0f;
        const float4* h4 = (const float4*)h[p];
#pragma unroll
        for (int k = 0; k < 32; k++) {
            float4 v = h4[k];
            a0 += w[4 * k + 0] * v.x;
            a1 += w[4 * k + 1] * v.y;
            a2 += w[4 * k + 2] * v.z;
            a3 += w[4 * k + 3] * v.w;
        }
        float dot = (a0 + a1) + (a2 + a3);
        float base = (g == 2) ? bn : px;
        hh[j] = base + (rst ? 0.0f : dot);
        __syncthreads();

        if (j < DD) {
            float sr = hh[d];            // xr + hr
            float sz = hh[128 + d];      // xz + hz
            float sn = hh[256 + d];      // hn + bhn
            float rg = 1.0f / (1.0f + __expf(-sr));
            float zg = 1.0f / (1.0f + __expf(-sz));
            float ng = tanhf(pxn + rg * sn);
            float hp = rst ? 0.0f : h[p][d];
            float nh = (1.0f - zg) * ng + zg * hp;
            h[p ^ 1][d] = nh;
            ys[((size_t)t * BB + b) * DD + d] = nh;
        }
        __syncthreads();

        p ^= 1;
        px = npx; pxn = npxn; rst = nrst;
    }
}

// ---------------------------------------------------------------------------
extern "C" void kernel_launch(void* const* d_in, const int* in_sizes, int n_in,
                              void* d_out, int out_size) {
    const float* x      = (const float*)d_in[0];
    const void*  resets = d_in[1];
    const float* Wi     = (const float*)d_in[2];
    const float* bi     = (const float*)d_in[3];
    const float* Wh     = (const float*)d_in[4];
    const float* bhn    = (const float*)d_in[5];
    float* ys = (float*)d_out;

    probe_resets_kernel<<<1, 256>>>((const unsigned int*)resets);
    gemm_xi_kernel<<<148, 384>>>(x, Wi, bi);
    gru_scan_kernel<<<BB, 384>>>(resets, Wh, bhn, ys);
}